// round 5
// baseline (speedup 1.0000x reference)
#include <cuda_runtime.h>
#include <cstdint>

// LIF forward scan:
//   v_t = BETA * v_{t-1} * (1 - s_{t-1}) + i_t   (hard reset)
//   s_t = (v_t >= 1.0)
// Outputs: spikes (B,T,H), membrane (B,T,H), v_final (B,H) — concatenated in d_out.
//
// R5: input loads via cp.async (LDGSTS) into a 6-stage smem ring. LDGSTS has no
// per-warp outstanding-depth cap (unlike LDG, ~55), so in-flight read bytes
// scale to ~20MB chip-wide, past the latency-BW product under loaded latency.

#define LIF_BETA 0.904837f

static constexpr int Bc = 16;
static constexpr int Tc = 1024;
static constexpr int Hc = 2048;
static constexpr int CHUNK  = 32;            // time steps per stage
static constexpr int NSTAGE = 6;             // smem ring depth
static constexpr int NCHUNK = Tc / CHUNK;    // 32

__device__ __forceinline__ void cp_async16(uint32_t saddr, const void* gsrc) {
    asm volatile("cp.async.cg.shared.global [%0], [%1], 16;\n"
                 :: "r"(saddr), "l"(gsrc));
}
__device__ __forceinline__ void cp_commit() {
    asm volatile("cp.async.commit_group;\n");
}
template <int N>
__device__ __forceinline__ void cp_wait() {
    asm volatile("cp.async.wait_group %0;\n" :: "n"(N));
}

__global__ __launch_bounds__(32)
void lif_kernel(const float* __restrict__ in,   // (B, T, H)
                const float* __restrict__ v0,   // (B, H)
                float* __restrict__ out)        // [spikes | membrane | v_final]
{
    // stage[s][e][lane]: time-step e of stage s, one float per chain(lane).
    __shared__ float stage[NSTAGE][CHUNK][32];

    const int lane = threadIdx.x;
    const int idx  = blockIdx.x * 32 + lane;        // chain id = b*H + h
    const int b    = idx >> 11;                     // / 2048
    const int h0   = (blockIdx.x * 32) & (Hc - 1);  // block's h start (32-aligned)

    const size_t plane = (size_t)Bc * Tc * Hc;
    float* __restrict__ spikes = out;
    float* __restrict__ mem    = out + plane;
    float* __restrict__ vfin   = out + 2 * plane;

    // Row t of this block's 32 chains: 128B-aligned, contiguous 32 floats.
    const size_t rowbase = (size_t)b * Tc * Hc + h0;

    // cp.async work split: 32 rows x 8 segments of 16B = 256 copies per stage,
    // 8 per thread. linear = k*32 + lane; row = linear/8; seg = linear%8.
    auto issue_stage = [&](int c) {
        const int st = c % NSTAGE;
#pragma unroll
        for (int k = 0; k < 8; ++k) {
            const int linear = k * 32 + lane;
            const int row = linear >> 3;
            const int seg = linear & 7;
            uint32_t saddr = (uint32_t)__cvta_generic_to_shared(
                &stage[st][row][seg * 4]);
            const float* gsrc = in + rowbase
                              + (size_t)(c * CHUNK + row) * Hc + seg * 4;
            cp_async16(saddr, gsrc);
        }
    };

    // Prologue: fill NSTAGE-1 stages, one commit group each.
#pragma unroll
    for (int c = 0; c < NSTAGE - 1; ++c) {
        issue_stage(c);
        cp_commit();
    }

    float v = v0[idx];
    float s = 0.0f;

    for (int c = 0; c < NCHUNK; ++c) {
        // Keep exactly one commit per iteration (empty group at the tail) so
        // wait_group<NSTAGE-1> always means "group c is complete".
        if (c + NSTAGE - 1 < NCHUNK)
            issue_stage(c + NSTAGE - 1);
        cp_commit();
        cp_wait<NSTAGE - 1>();
        __syncwarp();

        const int st = c % NSTAGE;
#pragma unroll
        for (int e = 0; e < CHUNK; ++e) {
            const float x  = stage[st][e][lane];
            const float vr = (s != 0.0f) ? 0.0f : v;   // hard reset, s in {0,1}
            v = fmaf(LIF_BETA, vr, x);
            s = (v >= 1.0f) ? 1.0f : 0.0f;
            const size_t o = rowbase + (size_t)(c * CHUNK + e) * Hc + lane;
            __stcs(spikes + o, s);
            __stcs(mem + o, v);
        }
        // Order this consume before the cp.async that overwrites this stage
        // (issued NSTAGE-1 iterations from now by possibly-divergent lanes).
        __syncwarp();
    }

    vfin[idx] = v;
}

extern "C" void kernel_launch(void* const* d_in, const int* in_sizes, int n_in,
                              void* d_out, int out_size)
{
    const float* input = (const float*)d_in[0];   // (16, 1024, 2048) float32
    const float* v0    = (const float*)d_in[1];   // (16, 2048) float32
    float* out         = (float*)d_out;

    const int nthreads = Bc * Hc;                 // 32768 chains
    const int block = 32;
    const int grid  = (nthreads + block - 1) / block;  // 1024 blocks
    lif_kernel<<<grid, block>>>(input, v0, out);
}

// round 6
// speedup vs baseline: 1.0139x; 1.0139x over previous
#include <cuda_runtime.h>
#include <cstdint>

// LIF forward scan:
//   v_t = BETA * v_{t-1} * (1 - s_{t-1}) + i_t   (hard reset)
//   s_t = (v_t >= 1.0)
// Outputs: spikes (B,T,H), membrane (B,T,H), v_final (B,H) — concatenated in d_out.
//
// R6: 4 chains per thread (float4). Warp covers 128 contiguous h -> 512B DRAM
// bursts for the read stream and both write streams (vs 128B before), targeting
// DRAM row-buffer/turnaround efficiency, which R3/R5 showed is the binding
// constraint (~68% DRAM busy regardless of prefetch depth or mechanism).
// Reads go through a 6-stage cp.async smem ring; each thread copies and
// consumes exactly its own 16B segment per row, so per-thread wait_group
// ordering suffices (no warp syncs in the hot loop).

#define LIF_BETA 0.904837f

static constexpr int Bc = 16;
static constexpr int Tc = 1024;
static constexpr int Hc = 2048;
static constexpr int CPT = 4;                 // chains per thread
static constexpr int WH  = 32 * CPT;          // 128 h per warp/block
static constexpr int CHUNK  = 16;             // time steps per stage
static constexpr int NSTAGE = 6;              // ring depth (48KB smem)
static constexpr int NCHUNK = Tc / CHUNK;     // 64

__device__ __forceinline__ void cp_async16(uint32_t saddr, const void* gsrc) {
    asm volatile("cp.async.cg.shared.global [%0], [%1], 16;\n"
                 :: "r"(saddr), "l"(gsrc));
}
__device__ __forceinline__ void cp_commit() {
    asm volatile("cp.async.commit_group;\n");
}
template <int N>
__device__ __forceinline__ void cp_wait() {
    asm volatile("cp.async.wait_group %0;\n" :: "n"(N));
}

__global__ __launch_bounds__(32)
void lif_kernel(const float* __restrict__ in,   // (B, T, H)
                const float* __restrict__ v0,   // (B, H)
                float* __restrict__ out)        // [spikes | membrane | v_final]
{
    // stage[s][e][0..WH): time-step e of stage s, 128 floats (512B) per row.
    __shared__ float stage[NSTAGE][CHUNK][WH];  // 6*16*128*4 = 48KB

    const int lane = threadIdx.x;
    const int chain0 = blockIdx.x * WH + lane * CPT;  // first of 4 chains
    const int b  = chain0 >> 11;                      // / 2048 (same for all 4)
    const int h0 = (blockIdx.x * WH) & (Hc - 1);      // block's h start

    const size_t plane = (size_t)Bc * Tc * Hc;
    float* __restrict__ spikes = out;
    float* __restrict__ mem    = out + plane;
    float* __restrict__ vfin   = out + 2 * plane;

    // Row t of this block: 512B contiguous (128 floats), 128B aligned.
    const size_t rowbase = (size_t)b * Tc * Hc + h0;
    const int elem = lane * CPT;                      // this thread's float4 slot

    // Issue one stage: thread `lane` copies its own 16B segment of every row.
    auto issue_stage = [&](int c) {
        const int st = c % NSTAGE;
        const size_t gbase = rowbase + (size_t)c * CHUNK * Hc + elem;
#pragma unroll
        for (int e = 0; e < CHUNK; ++e) {
            uint32_t saddr = (uint32_t)__cvta_generic_to_shared(&stage[st][e][elem]);
            cp_async16(saddr, in + gbase + (size_t)e * Hc);
        }
    };

    // Prologue: fill NSTAGE-1 stages, one commit group each.
#pragma unroll
    for (int c = 0; c < NSTAGE - 1; ++c) {
        issue_stage(c);
        cp_commit();
    }

    // Load initial state (contiguous float4).
    float4 vi = *(const float4*)(v0 + chain0);
    float va = vi.x, vb = vi.y, vc = vi.z, vd = vi.w;
    float sa = 0.f, sb = 0.f, sc = 0.f, sd = 0.f;

    for (int c = 0; c < NCHUNK; ++c) {
        // One commit per iteration (empty at tail) keeps wait semantics exact:
        // after wait_group<NSTAGE-1>, stage c's copies (this thread's) are done.
        if (c + NSTAGE - 1 < NCHUNK)
            issue_stage(c + NSTAGE - 1);
        cp_commit();
        cp_wait<NSTAGE - 1>();

        const int st = c % NSTAGE;
#pragma unroll
        for (int e = 0; e < CHUNK; ++e) {
            const float4 x = *(const float4*)&stage[st][e][elem];

            float vr;
            vr = (sa != 0.f) ? 0.f : va;  va = fmaf(LIF_BETA, vr, x.x);  sa = (va >= 1.f) ? 1.f : 0.f;
            vr = (sb != 0.f) ? 0.f : vb;  vb = fmaf(LIF_BETA, vr, x.y);  sb = (vb >= 1.f) ? 1.f : 0.f;
            vr = (sc != 0.f) ? 0.f : vc;  vc = fmaf(LIF_BETA, vr, x.z);  sc = (vc >= 1.f) ? 1.f : 0.f;
            vr = (sd != 0.f) ? 0.f : vd;  vd = fmaf(LIF_BETA, vr, x.w);  sd = (vd >= 1.f) ? 1.f : 0.f;

            const size_t o = rowbase + (size_t)(c * CHUNK + e) * Hc + elem;
            const float4 sp = make_float4(sa, sb, sc, sd);
            const float4 vm = make_float4(va, vb, vc, vd);
            __stcs((float4*)(spikes + o), sp);
            __stcs((float4*)(mem + o), vm);
        }
    }

    *(float4*)(vfin + chain0) = make_float4(va, vb, vc, vd);
}

extern "C" void kernel_launch(void* const* d_in, const int* in_sizes, int n_in,
                              void* d_out, int out_size)
{
    const float* input = (const float*)d_in[0];   // (16, 1024, 2048) float32
    const float* v0    = (const float*)d_in[1];   // (16, 2048) float32
    float* out         = (float*)d_out;

    const int nchains = Bc * Hc;                  // 32768
    const int grid = nchains / WH;                // 256 blocks of 1 warp
    lif_kernel<<<grid, 32>>>(input, v0, out);
}

// round 7
// speedup vs baseline: 1.0715x; 1.0568x over previous
#include <cuda_runtime.h>
#include <cstdint>

// LIF forward scan:
//   v_t = BETA * v_{t-1} * (1 - s_{t-1}) + i_t   (hard reset)
//   s_t = (v_t >= 1.0)
// Outputs: spikes (B,T,H), membrane (B,T,H), v_final (B,H) — concatenated in d_out.
//
// R7: float4 chains + cp.async read ring (as R6), PLUS register-staged,
// stream-segregated output flushing: compute 8 steps holding outputs in
// registers, then write 8 rows of spikes back-to-back, then 8 rows of mem.
// Goal: longer single-stream DRAM run lengths -> fewer R/W turnarounds.

#define LIF_BETA 0.904837f

static constexpr int Bc = 16;
static constexpr int Tc = 1024;
static constexpr int Hc = 2048;
static constexpr int CPT = 4;                 // chains per thread
static constexpr int WH  = 32 * CPT;          // 128 h per warp/block
static constexpr int CHUNK  = 8;              // time steps per stage / flush batch
static constexpr int NSTAGE = 6;              // ring depth (24KB smem)
static constexpr int NCHUNK = Tc / CHUNK;     // 128

__device__ __forceinline__ void cp_async16(uint32_t saddr, const void* gsrc) {
    asm volatile("cp.async.cg.shared.global [%0], [%1], 16;\n"
                 :: "r"(saddr), "l"(gsrc));
}
__device__ __forceinline__ void cp_commit() {
    asm volatile("cp.async.commit_group;\n");
}
template <int N>
__device__ __forceinline__ void cp_wait() {
    asm volatile("cp.async.wait_group %0;\n" :: "n"(N));
}

__global__ __launch_bounds__(32)
void lif_kernel(const float* __restrict__ in,   // (B, T, H)
                const float* __restrict__ v0,   // (B, H)
                float* __restrict__ out)        // [spikes | membrane | v_final]
{
    __shared__ float stage[NSTAGE][CHUNK][WH];  // 6*8*128*4 = 24KB

    const int lane = threadIdx.x;
    const int chain0 = blockIdx.x * WH + lane * CPT;
    const int b  = chain0 >> 11;                      // / 2048
    const int h0 = (blockIdx.x * WH) & (Hc - 1);

    const size_t plane = (size_t)Bc * Tc * Hc;
    float* __restrict__ spikes = out;
    float* __restrict__ mem    = out + plane;
    float* __restrict__ vfin   = out + 2 * plane;

    const size_t rowbase = (size_t)b * Tc * Hc + h0;
    const int elem = lane * CPT;

    // Thread `lane` copies and later consumes exactly its own 16B segment of
    // each row -> per-thread cp.async wait_group ordering suffices, no syncs.
    auto issue_stage = [&](int c) {
        const int st = c % NSTAGE;
        const size_t gbase = rowbase + (size_t)c * CHUNK * Hc + elem;
#pragma unroll
        for (int e = 0; e < CHUNK; ++e) {
            uint32_t saddr = (uint32_t)__cvta_generic_to_shared(&stage[st][e][elem]);
            cp_async16(saddr, in + gbase + (size_t)e * Hc);
        }
    };

#pragma unroll
    for (int c = 0; c < NSTAGE - 1; ++c) {
        issue_stage(c);
        cp_commit();
    }

    float4 vi = *(const float4*)(v0 + chain0);
    float va = vi.x, vb = vi.y, vc = vi.z, vd = vi.w;
    float sa = 0.f, sb = 0.f, sc = 0.f, sd = 0.f;

    float4 spb[CHUNK];   // staged spike rows (this thread's float4)
    float4 vmb[CHUNK];   // staged membrane rows

    for (int c = 0; c < NCHUNK; ++c) {
        if (c + NSTAGE - 1 < NCHUNK)
            issue_stage(c + NSTAGE - 1);
        cp_commit();
        cp_wait<NSTAGE - 1>();

        const int st = c % NSTAGE;

        // Phase 1: compute CHUNK steps, outputs staged in registers.
#pragma unroll
        for (int e = 0; e < CHUNK; ++e) {
            const float4 x = *(const float4*)&stage[st][e][elem];
            float vr;
            vr = (sa != 0.f) ? 0.f : va;  va = fmaf(LIF_BETA, vr, x.x);  sa = (va >= 1.f) ? 1.f : 0.f;
            vr = (sb != 0.f) ? 0.f : vb;  vb = fmaf(LIF_BETA, vr, x.y);  sb = (vb >= 1.f) ? 1.f : 0.f;
            vr = (sc != 0.f) ? 0.f : vc;  vc = fmaf(LIF_BETA, vr, x.z);  sc = (vc >= 1.f) ? 1.f : 0.f;
            vr = (sd != 0.f) ? 0.f : vd;  vd = fmaf(LIF_BETA, vr, x.w);  sd = (vd >= 1.f) ? 1.f : 0.f;
            spb[e] = make_float4(sa, sb, sc, sd);
            vmb[e] = make_float4(va, vb, vc, vd);
        }

        const size_t obase = rowbase + (size_t)c * CHUNK * Hc + elem;

        // Phase 2: flush spike stream as one burst (CHUNK x 512B/warp).
#pragma unroll
        for (int e = 0; e < CHUNK; ++e)
            __stcs((float4*)(spikes + obase + (size_t)e * Hc), spb[e]);

        // Phase 3: flush membrane stream as one burst.
#pragma unroll
        for (int e = 0; e < CHUNK; ++e)
            __stcs((float4*)(mem + obase + (size_t)e * Hc), vmb[e]);
    }

    *(float4*)(vfin + chain0) = make_float4(va, vb, vc, vd);
}

extern "C" void kernel_launch(void* const* d_in, const int* in_sizes, int n_in,
                              void* d_out, int out_size)
{
    const float* input = (const float*)d_in[0];   // (16, 1024, 2048) float32
    const float* v0    = (const float*)d_in[1];   // (16, 2048) float32
    float* out         = (float*)d_out;

    const int nchains = Bc * Hc;                  // 32768
    const int grid = nchains / WH;                // 256 blocks of 1 warp
    lif_kernel<<<grid, 32>>>(input, v0, out);
}